// round 16
// baseline (speedup 1.0000x reference)
#include <cuda_runtime.h>

// ---------------- problem constants ----------------
#define N_IMG 2
#define A_ 9
#define C_ 80
#define H_ 100
#define W_ 152
#define HW_ 15200           // H*W
#define CHW_ (C_*HW_)       // 1,216,000
#define ACHW 10944000       // A*C*H*W per image
#define REG_PER_IMG (A_*4*HW_)
#define TOPN 1000
#define POSTN 100
#define SCAP 8192                 // candidate cap (12-bit pivot -> cnt ~2000)
#define CHUNK 512                 // floats per chunk
#define CPI (ACHW/CHUNK)          // 21375 chunks per image
#define NQUADS (CPI/4)            // 5343 quads; 3 tail chunks
#define NGROUPS ((CPI+31)/32)     // 668
#define THRESH_LOGIT -2.9444389791664403f   // log(0.05/0.95)
#define BBOX_CLIP 4.1351665567423556f       // log(1000/16)
#define IMW1 1215.0f
#define IMH1 799.0f
#define NMS_T 0.5f
#define FULLMASK 0xffffffffu
#define FRONT_BX 148                        // blocks per image
#define FRONT_TOTAL (FRONT_BX * N_IMG)      // 296 = 2/SM * 148 (guaranteed resident)
#define FRONT_WPI ((FRONT_BX * 256) >> 5)   // 1184 warps per image
#define RANK_CPW 8                          // candidates per warp
#define RANK_TASKS (SCAP / RANK_CPW)        // 1024 tasks per image

// ---------------- device scratch (static, no allocs) ----------------
__device__ unsigned            g_chunkmax[N_IMG][CPI];
__device__ unsigned            g_tick1, g_tick2, g_tick3;
__device__ unsigned            g_flag1, g_flag2, g_flag3;
__device__ unsigned            g_pivot_mono[N_IMG];
__device__ int                 g_count[N_IMG];
__device__ unsigned long long  g_cand[N_IMG][SCAP];
__device__ float               g_boxes[N_IMG][TOPN][4];
__device__ float4              g_obox[N_IMG][TOPN];
__device__ float               g_area[N_IMG][TOPN];
__device__ float               g_scores[N_IMG][TOPN];
__device__ int                 g_labels[N_IMG][TOPN];
__device__ unsigned            g_validmask[N_IMG][32];
__device__ unsigned            g_iou[N_IMG][TOPN][32];

// monotone mapping: float bits -> unsigned preserving > ordering
__device__ __forceinline__ unsigned mono_of(float x) {
    unsigned b = __float_as_uint(x);
    return b ^ ((unsigned)((int)b >> 31) | 0x80000000u);
}

// max of one 512-float chunk (4 float4 per lane), as mono key
__device__ __forceinline__ unsigned chunk_max(const float4* w) {
    float m0 = fmaxf(fmaxf(w[0].x, w[0].y), fmaxf(w[0].z, w[0].w));
    float m1 = fmaxf(fmaxf(w[1].x, w[1].y), fmaxf(w[1].z, w[1].w));
    float m2 = fmaxf(fmaxf(w[2].x, w[2].y), fmaxf(w[2].z, w[2].w));
    float m3 = fmaxf(fmaxf(w[3].x, w[3].y), fmaxf(w[3].z, w[3].w));
    float mx = fmaxf(fmaxf(m0, m1), fmaxf(m2, m3));
    return __reduce_max_sync(FULLMASK, mono_of(mx));
}

// === 1: persistent front: sweep -> pivot -> collect -> rank -> IoU ========
// 296 blocks, all co-resident (launch_bounds(256,2): 2/SM * 148 = 296).
__global__ __launch_bounds__(256, 2) void front_kernel(
        const float* __restrict__ cls,
        const float* __restrict__ reg,
        const float* __restrict__ anchors) {
    const int n    = blockIdx.y;
    const int tid  = threadIdx.x;
    const int lane = tid & 31;
    const int bwid = tid >> 5;
    const int gw   = (blockIdx.x * 256 + tid) >> 5;   // warp id within image
    const float4* base = reinterpret_cast<const float4*>(cls + (size_t)n * ACHW);

    // ---------- phase A: chunk-max sweep (4 chunks / 16 float4 per iter) ---
    for (int q = gw; q < NQUADS; q += FRONT_WPI) {
        const float4* p = base + (size_t)q * 512;
        float4 w[16];
#pragma unroll
        for (int e = 0; e < 16; e++) w[e] = p[e * 32 + lane];  // 16 loads in flight
        unsigned mx0 = chunk_max(w);
        unsigned mx1 = chunk_max(w + 4);
        unsigned mx2 = chunk_max(w + 8);
        unsigned mx3 = chunk_max(w + 12);
        if (lane == 0) {
            g_chunkmax[n][q * 4 + 0] = mx0;
            g_chunkmax[n][q * 4 + 1] = mx1;
            g_chunkmax[n][q * 4 + 2] = mx2;
            g_chunkmax[n][q * 4 + 3] = mx3;
        }
    }
    if (gw == 0) {   // 3 tail chunks
        const float4* p = base + (size_t)(NQUADS * 4) * 128;
        float4 w[12];
#pragma unroll
        for (int e = 0; e < 12; e++) w[e] = p[e * 32 + lane];
        unsigned mx0 = chunk_max(w);
        unsigned mx1 = chunk_max(w + 4);
        unsigned mx2 = chunk_max(w + 8);
        if (lane == 0) {
            g_chunkmax[n][NQUADS * 4 + 0] = mx0;
            g_chunkmax[n][NQUADS * 4 + 1] = mx1;
            g_chunkmax[n][NQUADS * 4 + 2] = mx2;
        }
    }

    // ---------- barrier 1: last block computes pivots, others spin --------
    __shared__ bool s_last;
    __shared__ __align__(16) unsigned sh[N_IMG][4096];
    __shared__ __align__(16) unsigned ssum[N_IMG][128];
    __threadfence();
    __syncthreads();
    if (tid == 0) s_last = (atomicAdd(&g_tick1, 1u) == FRONT_TOTAL - 1);
    __syncthreads();
    if (s_last) {
        // fast pivot tail: two 128-thread halves, one image each
        const int img = tid >> 7;
        const int lt  = tid & 127;
        const unsigned* __restrict__ CM = g_chunkmax[img];
        for (int i = lt; i < 4096; i += 128) sh[img][i] = 0u;
        __syncthreads();
        for (int b = 0; b < 168; b += 8) {
            unsigned v[8]; bool ok[8];
#pragma unroll
            for (int k = 0; k < 8; k++) {
                int idx = lt + (b + k) * 128;
                ok[k] = idx < CPI;
                v[k] = ok[k] ? CM[idx] : 0u;
            }
#pragma unroll
            for (int k = 0; k < 8; k++)
                if (ok[k]) atomicAdd(&sh[img][v[k] >> 20], 1u);
        }
        __syncthreads();
        {
            const int b0 = 4096 - 32 * (lt + 1);
            unsigned h[32];
#pragma unroll
            for (int i = 0; i < 32; i++) h[i] = sh[img][b0 + i];
            unsigned s = 0;
#pragma unroll
            for (int i = 0; i < 32; i++) s += h[i];
            ssum[img][lt] = s;
            __syncthreads();
            for (int off = 1; off < 128; off <<= 1) {
                unsigned add = (lt >= off) ? ssum[img][lt - off] : 0u;
                __syncthreads();
                ssum[img][lt] += add;
                __syncthreads();
            }
            unsigned incl = ssum[img][lt];
            unsigned excl = incl - s;
            if (excl < TOPN && incl >= TOPN) {
                unsigned run = excl;
                for (int i = 31; i >= 0; i--) {
                    run += h[i];
                    if (run >= TOPN) {
                        g_pivot_mono[img] = (unsigned)(b0 + i) << 20;
                        break;
                    }
                }
            }
        }
        __threadfence();
        __syncthreads();
        if (tid == 0) *(volatile unsigned*)&g_flag1 = 1u;
    } else {
        if (tid == 0) { while (*(volatile unsigned*)&g_flag1 == 0u) __nanosleep(128); }
        __syncthreads();
    }

    // ---------- phase C: collect candidates (all blocks) -------------------
    const unsigned pivot = *(volatile unsigned*)&g_pivot_mono[n];
    for (int g = gw; g < NGROUPS; g += FRONT_WPI) {
        int chbase = g * 32;
        int ch_l = chbase + lane;
        bool active = (ch_l < CPI) && (g_chunkmax[n][ch_l] >= pivot);
        unsigned act = __ballot_sync(FULLMASK, active);
        while (act) {
            int c = __ffs(act) - 1;
            act &= act - 1;
            int ch = chbase + c;
            const float4* p = base + (size_t)ch * 128;
#pragma unroll
            for (int e = 0; e < 4; e++) {
                float4 v = p[e * 32 + lane];
                float vals[4] = {v.x, v.y, v.z, v.w};
#pragma unroll
                for (int k = 0; k < 4; k++) {
                    float x = vals[k];
                    if (x > THRESH_LOGIT) {
                        unsigned mono = mono_of(x);
                        if (mono >= pivot) {
                            int m   = ch * CHUNK + (e * 32 + lane) * 4 + k;
                            int a   = m / CHW_;
                            int rem = m - a * CHW_;
                            int c2  = rem / HW_;
                            int hw  = rem - c2 * HW_;
                            unsigned ref_idx = (unsigned)((hw * A_ + a) * C_ + c2);
                            int pos = atomicAdd(&g_count[n], 1);
                            if (pos < SCAP)
                                g_cand[n][pos] =
                                    ((unsigned long long)mono << 32) |
                                    (0xFFFFFFFFu - ref_idx);
                        }
                    }
                }
            }
        }
    }

    // ---------- barrier 2: full join (all candidates written) --------------
    __threadfence();
    __syncthreads();
    if (tid == 0) {
        unsigned t = atomicAdd(&g_tick2, 1u);
        if (t == FRONT_TOTAL - 1) *(volatile unsigned*)&g_flag2 = 1u;
        else while (*(volatile unsigned*)&g_flag2 == 0u) __nanosleep(128);
    }
    __syncthreads();

    // ---------- phase E: enumeration rank (8 cand/warp) + decode -----------
    // (return-free so every thread reaches barrier 3)
    const int fb    = blockIdx.y * gridDim.x + blockIdx.x;   // 0..295
    const int gtask = fb * 8 + bwid;                         // 0..2367
    if (gtask < N_IMG * RANK_TASKS) {
        const int rn    = gtask >> 10;                       // image
        const int cand0 = (gtask & (RANK_TASKS - 1)) * RANK_CPW;
        int cnt = *(volatile int*)&g_count[rn];
        if (cnt > SCAP) cnt = SCAP;
        const int mycand = cand0 + lane;                     // valid for lane < 8

        if (lane < RANK_CPW && mycand >= cnt && mycand < TOPN) {
            g_boxes[rn][mycand][0] = 0.f; g_boxes[rn][mycand][1] = 0.f;
            g_boxes[rn][mycand][2] = 0.f; g_boxes[rn][mycand][3] = 0.f;
            g_scores[rn][mycand] = -1.0f;
            g_labels[rn][mycand] = 0;
            g_obox[rn][mycand] = make_float4(0.f, 0.f, 0.f, 0.f);
            g_area[rn][mycand] = 1.0f;
        }
        if (cand0 < cnt) {                 // warp-uniform
            const unsigned long long* __restrict__ K = g_cand[rn];
            unsigned long long kl = 0ULL;
            if (lane < RANK_CPW && mycand < cnt) kl = K[mycand];
            unsigned long long k[RANK_CPW];
#pragma unroll
            for (int i = 0; i < RANK_CPW; i++) k[i] = __shfl_sync(FULLMASK, kl, i);

            int r[RANK_CPW];
#pragma unroll
            for (int i = 0; i < RANK_CPW; i++) r[i] = 0;
            int j = lane;
            for (; j + 32 < cnt; j += 64) {
                unsigned long long v0 = K[j], v1 = K[j + 32];
#pragma unroll
                for (int i = 0; i < RANK_CPW; i++) {
                    r[i] += (v0 > k[i]);
                    r[i] += (v1 > k[i]);
                }
            }
            if (j < cnt) {
                unsigned long long v0 = K[j];
#pragma unroll
                for (int i = 0; i < RANK_CPW; i++) r[i] += (v0 > k[i]);
            }
#pragma unroll
            for (int i = 0; i < RANK_CPW; i++) r[i] = __reduce_add_sync(FULLMASK, r[i]);

            if (lane < RANK_CPW && mycand < cnt) {
                const int rank = r[lane];
                if (rank < TOPN) {
                    const unsigned long long mykey = k[lane];
                    unsigned mono = (unsigned)(mykey >> 32);
                    unsigned bits = (mono & 0x80000000u) ? (mono ^ 0x80000000u) : ~mono;
                    float logit = __uint_as_float(bits);
                    float score = 1.0f / (1.0f + expf(-logit));

                    unsigned ref_idx = 0xFFFFFFFFu - (unsigned)(mykey & 0xFFFFFFFFull);
                    int c   = (int)(ref_idx % C_);
                    int loc = (int)(ref_idx / C_);
                    int a   = loc % A_;
                    int hw  = loc / A_;

                    const float* anc = anchors + 4 * (size_t)loc;
                    float ax1 = anc[0], ay1 = anc[1], ax2 = anc[2], ay2 = anc[3];
                    float wdt = ax2 - ax1 + 1.0f;
                    float hgt = ay2 - ay1 + 1.0f;
                    float ctrx = ax1 + 0.5f * wdt;
                    float ctry = ay1 + 0.5f * hgt;

                    size_t rb = (size_t)rn * REG_PER_IMG + (size_t)a * 4 * HW_ + hw;
                    float dx = reg[rb]               / 10.0f;
                    float dy = reg[rb + HW_]         / 10.0f;
                    float dw = fminf(reg[rb + 2 * HW_] / 5.0f, BBOX_CLIP);
                    float dh = fminf(reg[rb + 3 * HW_] / 5.0f, BBOX_CLIP);

                    float pcx = dx * wdt + ctrx;
                    float pcy = dy * hgt + ctry;
                    float pw  = expf(dw) * wdt;
                    float ph  = expf(dh) * hgt;

                    float x1 = pcx - 0.5f * pw;
                    float y1 = pcy - 0.5f * ph;
                    float x2 = pcx + 0.5f * pw - 1.0f;
                    float y2 = pcy + 0.5f * ph - 1.0f;
                    x1 = fminf(fmaxf(x1, 0.0f), IMW1);
                    y1 = fminf(fmaxf(y1, 0.0f), IMH1);
                    x2 = fminf(fmaxf(x2, 0.0f), IMW1);
                    y2 = fminf(fmaxf(y2, 0.0f), IMH1);

                    bool valid = (score > 0.0f) &&
                                 (x2 - x1 + 1.0f >= 0.0f) &&
                                 (y2 - y1 + 1.0f >= 0.0f);
                    int label = c + 1;

                    g_boxes[rn][rank][0] = x1; g_boxes[rn][rank][1] = y1;
                    g_boxes[rn][rank][2] = x2; g_boxes[rn][rank][3] = y2;
                    g_scores[rn][rank] = score;
                    g_labels[rn][rank] = label;
                    float off = (float)label * 4096.0f;
                    g_obox[rn][rank] = make_float4(x1 + off, y1 + off, x2 + off, y2 + off);
                    g_area[rn][rank] = (x2 - x1 + 1.0f) * (y2 - y1 + 1.0f);
                    if (valid) atomicOr(&g_validmask[rn][rank >> 5], 1u << (rank & 31));
                }
            }
        }
    }

    // ---------- barrier 3: all boxes decoded/scattered ----------------------
    __threadfence();
    __syncthreads();
    if (tid == 0) {
        unsigned t = atomicAdd(&g_tick3, 1u);
        if (t == FRONT_TOTAL - 1) *(volatile unsigned*)&g_flag3 = 1u;
        else while (*(volatile unsigned*)&g_flag3 == 0u) __nanosleep(128);
    }
    __syncthreads();

    // ---------- phase F: triangle IoU bitmask (warp = one (img,row)) --------
    // Greedy NMS suppression only propagates forward; words < row's own word
    // are never written and stay 0 (device globals are zero-initialized).
    {
        const int fw = fb * 8 + bwid;            // 0..2367; tasks: 0..1999
        if (fw < N_IMG * TOPN) {
            const int fn = fw / TOPN;
            const int fi = fw - fn * TOPN;
            const int iw0 = fi >> 5;
            float4 bi = g_obox[fn][fi];
            float ai  = g_area[fn][fi];
#pragma unroll 2
            for (int word = iw0; word < 32; word++) {
                int j  = word * 32 + lane;
                int jc = (j < TOPN) ? j : (TOPN - 1);
                float4 bj = g_obox[fn][jc];
                float aj  = g_area[fn][jc];
                float iw = fmaxf(fminf(bi.z, bj.z) - fmaxf(bi.x, bj.x) + 1.0f, 0.0f);
                float ih = fmaxf(fminf(bi.w, bj.w) - fmaxf(bi.y, bj.y) + 1.0f, 0.0f);
                float inter = iw * ih;
                float iou = inter / (ai + aj - inter);
                bool cond = (j < TOPN) && (iou > NMS_T);
                unsigned bal = __ballot_sync(FULLMASK, cond);
                if (lane == 0) g_iou[fn][fi][word] = bal;
            }
        }
    }
}

// -------- 2: serial NMS scan (warp 0) + final top-100 emit + reset --------
__global__ __launch_bounds__(1024) void nms_emit_kernel(float* __restrict__ out) {
    __shared__ unsigned s_keepw[32];
    __shared__ int s_warpoff[32];
    __shared__ int s_tot;
    const int n = blockIdx.x;
    const int tid = threadIdx.x;
    const int lane = tid & 31, w = tid >> 5;

    if (tid < 32) s_keepw[tid] = 0u;
    __syncthreads();

    // warp 0: sequential greedy scan with prefetch + early exit
    if (tid < 32) {
        unsigned supp = 0u;
        unsigned vmw  = g_validmask[n][lane];
        const unsigned* __restrict__ M = &g_iou[n][0][0];
        int kept = 0;
        bool early = false;

        unsigned mN[32];
#pragma unroll
        for (int j = 0; j < 32; j++) mN[j] = M[j * 32 + lane];

#pragma unroll 1
        for (int c = 0; c < 32; c++) {
            unsigned m[32];
#pragma unroll
            for (int j = 0; j < 32; j++) m[j] = mN[j];
            if (c < 31) {
#pragma unroll
                for (int j = 0; j < 32; j++) mN[j] = M[((c + 1) * 32 + j) * 32 + lane];
            }
            unsigned cur = __shfl_sync(FULLMASK, supp, c);
            unsigned vw  = __shfl_sync(FULLMASK, vmw, c);
            unsigned vals[32];
#pragma unroll
            for (int j = 0; j < 32; j++) vals[j] = __shfl_sync(FULLMASK, m[j], c);

            unsigned keepw = 0u;
#pragma unroll
            for (int j = 0; j < 32; j++) {
                unsigned ki = (vw >> j) & (~(cur >> j)) & 1u;
                keepw |= ki << j;
                unsigned msk = 0u - ki;
                cur  |= vals[j] & msk;
                supp |= m[j]    & msk;
            }
            if (lane == 0) s_keepw[c] = keepw;
            kept += __popc(keepw);
            if (kept >= POSTN) { early = true; break; }
        }
        if (lane == 0) s_tot = early ? TOPN : kept;
    }
    __syncthreads();

    // parallel ranking: kept (in order), then non-kept (in order)
    const bool in = tid < TOPN;
    int k = (in && ((s_keepw[w] >> lane) & 1u)) ? 1 : 0;
    unsigned wb = __ballot_sync(FULLMASK, k);
    int pre = __popc(wb & ((1u << lane) - 1u));
    if (lane == 0) s_warpoff[w] = __popc(wb);
    __syncthreads();
    if (tid == 0) {
        int s = 0;
        for (int x = 0; x < 32; x++) { int t2 = s_warpoff[x]; s_warpoff[x] = s; s += t2; }
    }
    __syncthreads();

    if (in) {
        int kept_before = s_warpoff[w] + pre;
        int r = k ? kept_before : (s_tot + (tid - kept_before));
        if (r < POSTN) {
            int base_b = n * POSTN * 4;
            int base_s = N_IMG * POSTN * 4 + n * POSTN;
            int base_l = N_IMG * POSTN * 5 + n * POSTN;
            out[base_b + r * 4 + 0] = g_boxes[n][tid][0];
            out[base_b + r * 4 + 1] = g_boxes[n][tid][1];
            out[base_b + r * 4 + 2] = g_boxes[n][tid][2];
            out[base_b + r * 4 + 3] = g_boxes[n][tid][3];
            out[base_s + r] = k ? g_scores[n][tid] : -1.0f;
            out[base_l + r] = k ? (float)g_labels[n][tid] : 0.0f;
        }
    }

    // reset per-replay state for the next graph replay
    if (tid < 32) g_validmask[n][tid] = 0u;
    if (tid == 0) {
        g_count[n] = 0;
        if (n == 0) {
            g_tick1 = 0; g_tick2 = 0; g_tick3 = 0;
            g_flag1 = 0; g_flag2 = 0; g_flag3 = 0;
        }
    }
}

// ---------------- host launch ----------------
extern "C" void kernel_launch(void* const* d_in, const int* in_sizes, int n_in,
                              void* d_out, int out_size) {
    (void)in_sizes; (void)n_in; (void)out_size;
    const float* box_cls = (const float*)d_in[0];
    const float* box_reg = (const float*)d_in[1];
    const float* anchors = (const float*)d_in[2];
    float* out = (float*)d_out;

    front_kernel<<<dim3(FRONT_BX, N_IMG), 256>>>(box_cls, box_reg, anchors);
    nms_emit_kernel<<<N_IMG, 1024>>>(out);
}

// round 17
// speedup vs baseline: 1.3209x; 1.3209x over previous
#include <cuda_runtime.h>

// ---------------- problem constants ----------------
#define N_IMG 2
#define A_ 9
#define C_ 80
#define H_ 100
#define W_ 152
#define HW_ 15200           // H*W
#define CHW_ (C_*HW_)       // 1,216,000
#define ACHW 10944000       // A*C*H*W per image
#define REG_PER_IMG (A_*4*HW_)
#define TOPN 1000
#define POSTN 100
#define SCAP 8192                 // candidate cap (12-bit pivot -> cnt ~2000)
#define CHUNK 512                 // floats per chunk
#define CPI (ACHW/CHUNK)          // 21375 chunks per image
#define NQUADS (CPI/4)            // 5343 quads; 3 tail chunks
#define NGROUPS ((CPI+31)/32)     // 668
#define THRESH_LOGIT -2.9444389791664403f   // log(0.05/0.95)
#define BBOX_CLIP 4.1351665567423556f       // log(1000/16)
#define IMW1 1215.0f
#define IMH1 799.0f
#define NMS_T 0.5f
#define FULLMASK 0xffffffffu
#define FRONT_BX 148                        // blocks per image
#define FRONT_TOTAL (FRONT_BX * N_IMG)      // 296 = 2/SM * 148 (guaranteed resident)
#define FRONT_WPI ((FRONT_BX * 256) >> 5)   // 1184 warps per image
#define RANK_CPW 8                          // candidates per warp
#define RANK_TASKS (SCAP / RANK_CPW)        // 1024 tasks per image

// ---------------- device scratch (static, no allocs) ----------------
__device__ unsigned            g_chunkmax[N_IMG][CPI];
__device__ unsigned            g_hist[N_IMG][4096];   // chunkmax histogram (12-bit)
__device__ unsigned            g_tick1, g_tick2;
__device__ unsigned            g_flag1, g_flag2;
__device__ unsigned            g_pivot_mono[N_IMG];
__device__ int                 g_count[N_IMG];
__device__ unsigned long long  g_cand[N_IMG][SCAP];
__device__ float               g_boxes[N_IMG][TOPN][4];
__device__ float4              g_obox[N_IMG][TOPN];
__device__ float               g_area[N_IMG][TOPN];
__device__ float               g_scores[N_IMG][TOPN];
__device__ int                 g_labels[N_IMG][TOPN];
__device__ unsigned            g_validmask[N_IMG][32];
__device__ unsigned            g_iou[N_IMG][TOPN][32];

// monotone mapping: float bits -> unsigned preserving > ordering
__device__ __forceinline__ unsigned mono_of(float x) {
    unsigned b = __float_as_uint(x);
    return b ^ ((unsigned)((int)b >> 31) | 0x80000000u);
}

// max of one 512-float chunk (4 float4 per lane), as mono key
__device__ __forceinline__ unsigned chunk_max(const float4* w) {
    float m0 = fmaxf(fmaxf(w[0].x, w[0].y), fmaxf(w[0].z, w[0].w));
    float m1 = fmaxf(fmaxf(w[1].x, w[1].y), fmaxf(w[1].z, w[1].w));
    float m2 = fmaxf(fmaxf(w[2].x, w[2].y), fmaxf(w[2].z, w[2].w));
    float m3 = fmaxf(fmaxf(w[3].x, w[3].y), fmaxf(w[3].z, w[3].w));
    float mx = fmaxf(fmaxf(m0, m1), fmaxf(m2, m3));
    return __reduce_max_sync(FULLMASK, mono_of(mx));
}

// === 1: persistent front: sweep(+hist) -> pivot scan -> collect -> rank ===
// 296 blocks, all co-resident (launch_bounds(256,2): 2/SM * 148 = 296).
__global__ __launch_bounds__(256, 2) void front_kernel(
        const float* __restrict__ cls,
        const float* __restrict__ reg,
        const float* __restrict__ anchors) {
    const int n    = blockIdx.y;
    const int tid  = threadIdx.x;
    const int lane = tid & 31;
    const int bwid = tid >> 5;
    const int gw   = (blockIdx.x * 256 + tid) >> 5;   // warp id within image
    const float4* base = reinterpret_cast<const float4*>(cls + (size_t)n * ACHW);

    __shared__ unsigned shist[4096];                  // block-local chunkmax hist
    __shared__ unsigned ssum[N_IMG][128];
    __shared__ bool s_last;
    for (int i = tid; i < 4096; i += 256) shist[i] = 0u;
    __syncthreads();

    // ---------- phase A: chunk-max sweep + on-the-fly histogram ------------
    for (int q = gw; q < NQUADS; q += FRONT_WPI) {
        const float4* p = base + (size_t)q * 512;
        float4 w[16];
#pragma unroll
        for (int e = 0; e < 16; e++) w[e] = p[e * 32 + lane];  // 16 loads in flight
        unsigned mx0 = chunk_max(w);
        unsigned mx1 = chunk_max(w + 4);
        unsigned mx2 = chunk_max(w + 8);
        unsigned mx3 = chunk_max(w + 12);
        if (lane == 0) {
            g_chunkmax[n][q * 4 + 0] = mx0;
            g_chunkmax[n][q * 4 + 1] = mx1;
            g_chunkmax[n][q * 4 + 2] = mx2;
            g_chunkmax[n][q * 4 + 3] = mx3;
            atomicAdd(&shist[mx0 >> 20], 1u);
            atomicAdd(&shist[mx1 >> 20], 1u);
            atomicAdd(&shist[mx2 >> 20], 1u);
            atomicAdd(&shist[mx3 >> 20], 1u);
        }
    }
    if (gw == 0) {   // 3 tail chunks
        const float4* p = base + (size_t)(NQUADS * 4) * 128;
        float4 w[12];
#pragma unroll
        for (int e = 0; e < 12; e++) w[e] = p[e * 32 + lane];
        unsigned mx0 = chunk_max(w);
        unsigned mx1 = chunk_max(w + 4);
        unsigned mx2 = chunk_max(w + 8);
        if (lane == 0) {
            g_chunkmax[n][NQUADS * 4 + 0] = mx0;
            g_chunkmax[n][NQUADS * 4 + 1] = mx1;
            g_chunkmax[n][NQUADS * 4 + 2] = mx2;
            atomicAdd(&shist[mx0 >> 20], 1u);
            atomicAdd(&shist[mx1 >> 20], 1u);
            atomicAdd(&shist[mx2 >> 20], 1u);
        }
    }
    __syncthreads();
    // flush nonzero bins to the global per-image histogram
    for (int i = tid; i < 4096; i += 256) {
        unsigned v = shist[i];
        if (v) atomicAdd(&g_hist[n][i], v);
    }

    // ---------- barrier 1: last block scans histograms, others spin --------
    __threadfence();
    __syncthreads();
    if (tid == 0) s_last = (atomicAdd(&g_tick1, 1u) == FRONT_TOTAL - 1);
    __syncthreads();
    if (s_last) {
        // scan the 4096-bin hist from the top; 128 threads per image
        const int img = tid >> 7;
        const int lt  = tid & 127;
        const int b0 = 4096 - 32 * (lt + 1);
        unsigned h[32];
#pragma unroll
        for (int i = 0; i < 32; i++) h[i] = g_hist[img][b0 + i];
        unsigned s = 0;
#pragma unroll
        for (int i = 0; i < 32; i++) s += h[i];
        ssum[img][lt] = s;
        __syncthreads();
        for (int off = 1; off < 128; off <<= 1) {
            unsigned add = (lt >= off) ? ssum[img][lt - off] : 0u;
            __syncthreads();
            ssum[img][lt] += add;
            __syncthreads();
        }
        unsigned incl = ssum[img][lt];
        unsigned excl = incl - s;
        if (excl < TOPN && incl >= TOPN) {      // unique crossing thread
            unsigned run = excl;
            for (int i = 31; i >= 0; i--) {     // bins descending from top
                run += h[i];
                if (run >= TOPN) {
                    g_pivot_mono[img] = (unsigned)(b0 + i) << 20;
                    break;
                }
            }
        }
        __threadfence();
        __syncthreads();
        if (tid == 0) *(volatile unsigned*)&g_flag1 = 1u;
    } else {
        if (tid == 0) { while (*(volatile unsigned*)&g_flag1 == 0u) __nanosleep(128); }
        __syncthreads();
    }

    // ---------- phase C: collect candidates (all blocks) -------------------
    const unsigned pivot = *(volatile unsigned*)&g_pivot_mono[n];
    for (int g = gw; g < NGROUPS; g += FRONT_WPI) {
        int chbase = g * 32;
        int ch_l = chbase + lane;
        bool active = (ch_l < CPI) && (g_chunkmax[n][ch_l] >= pivot);
        unsigned act = __ballot_sync(FULLMASK, active);
        while (act) {
            int c = __ffs(act) - 1;
            act &= act - 1;
            int ch = chbase + c;
            const float4* p = base + (size_t)ch * 128;
#pragma unroll
            for (int e = 0; e < 4; e++) {
                float4 v = p[e * 32 + lane];
                float vals[4] = {v.x, v.y, v.z, v.w};
#pragma unroll
                for (int k = 0; k < 4; k++) {
                    float x = vals[k];
                    if (x > THRESH_LOGIT) {
                        unsigned mono = mono_of(x);
                        if (mono >= pivot) {
                            int m   = ch * CHUNK + (e * 32 + lane) * 4 + k;
                            int a   = m / CHW_;
                            int rem = m - a * CHW_;
                            int c2  = rem / HW_;
                            int hw  = rem - c2 * HW_;
                            unsigned ref_idx = (unsigned)((hw * A_ + a) * C_ + c2);
                            int pos = atomicAdd(&g_count[n], 1);
                            if (pos < SCAP)
                                g_cand[n][pos] =
                                    ((unsigned long long)mono << 32) |
                                    (0xFFFFFFFFu - ref_idx);
                        }
                    }
                }
            }
        }
    }

    // ---------- barrier 2: full join (all candidates written) --------------
    __threadfence();
    __syncthreads();
    if (tid == 0) {
        unsigned t = atomicAdd(&g_tick2, 1u);
        if (t == FRONT_TOTAL - 1) *(volatile unsigned*)&g_flag2 = 1u;
        else while (*(volatile unsigned*)&g_flag2 == 0u) __nanosleep(128);
    }
    __syncthreads();

    // ---------- phase E: enumeration rank (8 cand/warp) + decode -----------
    const int fb    = blockIdx.y * gridDim.x + blockIdx.x;   // 0..295
    const int gtask = fb * 8 + bwid;                         // 0..2367
    if (gtask >= N_IMG * RANK_TASKS) return;
    const int rn    = gtask >> 10;                           // image
    const int cand0 = (gtask & (RANK_TASKS - 1)) * RANK_CPW;
    int cnt = *(volatile int*)&g_count[rn];
    if (cnt > SCAP) cnt = SCAP;
    const int mycand = cand0 + lane;                         // valid for lane < 8

    if (lane < RANK_CPW && mycand >= cnt && mycand < TOPN) {
        g_boxes[rn][mycand][0] = 0.f; g_boxes[rn][mycand][1] = 0.f;
        g_boxes[rn][mycand][2] = 0.f; g_boxes[rn][mycand][3] = 0.f;
        g_scores[rn][mycand] = -1.0f;
        g_labels[rn][mycand] = 0;
        g_obox[rn][mycand] = make_float4(0.f, 0.f, 0.f, 0.f);
        g_area[rn][mycand] = 1.0f;
    }
    if (cand0 >= cnt) return;

    const unsigned long long* __restrict__ K = g_cand[rn];
    unsigned long long kl = 0ULL;
    if (lane < RANK_CPW && mycand < cnt) kl = K[mycand];
    unsigned long long k[RANK_CPW];
#pragma unroll
    for (int i = 0; i < RANK_CPW; i++) k[i] = __shfl_sync(FULLMASK, kl, i);

    int r[RANK_CPW];
#pragma unroll
    for (int i = 0; i < RANK_CPW; i++) r[i] = 0;
    int j = lane;
    for (; j + 32 < cnt; j += 64) {
        unsigned long long v0 = K[j], v1 = K[j + 32];
#pragma unroll
        for (int i = 0; i < RANK_CPW; i++) {
            r[i] += (v0 > k[i]);
            r[i] += (v1 > k[i]);
        }
    }
    if (j < cnt) {
        unsigned long long v0 = K[j];
#pragma unroll
        for (int i = 0; i < RANK_CPW; i++) r[i] += (v0 > k[i]);
    }
#pragma unroll
    for (int i = 0; i < RANK_CPW; i++) r[i] = __reduce_add_sync(FULLMASK, r[i]);

    if (lane >= RANK_CPW || mycand >= cnt) return;
    const int rank = r[lane];
    if (rank >= TOPN) return;
    const unsigned long long mykey = k[lane];

    // decode
    unsigned mono = (unsigned)(mykey >> 32);
    unsigned bits = (mono & 0x80000000u) ? (mono ^ 0x80000000u) : ~mono;
    float logit = __uint_as_float(bits);
    float score = 1.0f / (1.0f + expf(-logit));

    unsigned ref_idx = 0xFFFFFFFFu - (unsigned)(mykey & 0xFFFFFFFFull);
    int c   = (int)(ref_idx % C_);
    int loc = (int)(ref_idx / C_);
    int a   = loc % A_;
    int hw  = loc / A_;

    const float* anc = anchors + 4 * (size_t)loc;
    float ax1 = anc[0], ay1 = anc[1], ax2 = anc[2], ay2 = anc[3];
    float wdt = ax2 - ax1 + 1.0f;
    float hgt = ay2 - ay1 + 1.0f;
    float ctrx = ax1 + 0.5f * wdt;
    float ctry = ay1 + 0.5f * hgt;

    size_t rb = (size_t)rn * REG_PER_IMG + (size_t)a * 4 * HW_ + hw;
    float dx = reg[rb]               / 10.0f;
    float dy = reg[rb + HW_]         / 10.0f;
    float dw = fminf(reg[rb + 2 * HW_] / 5.0f, BBOX_CLIP);
    float dh = fminf(reg[rb + 3 * HW_] / 5.0f, BBOX_CLIP);

    float pcx = dx * wdt + ctrx;
    float pcy = dy * hgt + ctry;
    float pw  = expf(dw) * wdt;
    float ph  = expf(dh) * hgt;

    float x1 = pcx - 0.5f * pw;
    float y1 = pcy - 0.5f * ph;
    float x2 = pcx + 0.5f * pw - 1.0f;
    float y2 = pcy + 0.5f * ph - 1.0f;
    x1 = fminf(fmaxf(x1, 0.0f), IMW1);
    y1 = fminf(fmaxf(y1, 0.0f), IMH1);
    x2 = fminf(fmaxf(x2, 0.0f), IMW1);
    y2 = fminf(fmaxf(y2, 0.0f), IMH1);

    bool valid = (score > 0.0f) &&
                 (x2 - x1 + 1.0f >= 0.0f) &&
                 (y2 - y1 + 1.0f >= 0.0f);
    int label = c + 1;

    g_boxes[rn][rank][0] = x1; g_boxes[rn][rank][1] = y1;
    g_boxes[rn][rank][2] = x2; g_boxes[rn][rank][3] = y2;
    g_scores[rn][rank] = score;
    g_labels[rn][rank] = label;
    float off = (float)label * 4096.0f;
    g_obox[rn][rank] = make_float4(x1 + off, y1 + off, x2 + off, y2 + off);
    g_area[rn][rank] = (x2 - x1 + 1.0f) * (y2 - y1 + 1.0f);
    if (valid) atomicOr(&g_validmask[rn][rank >> 5], 1u << (rank & 31));
}

// ------- 2: IoU > 0.5 bitmask, TRIANGLE ONLY (words >= i's own word) ------
// Greedy NMS suppression only propagates forward; bits for j <= i never
// matter. Below-diagonal words are never written and stay 0 forever.
__global__ void iou_kernel() {
    const int lane = threadIdx.x;
    const int i    = blockIdx.x * blockDim.y + threadIdx.y;
    const int n    = blockIdx.z;
    if (i >= TOPN) return;
    const int w4 = blockIdx.y;
    const int iw_ = i >> 5;
    if (w4 * 4 + 3 < iw_) return;      // whole 4-word group below diagonal

    float4 bi = g_obox[n][i];
    float ai  = g_area[n][i];

#pragma unroll
    for (int w = 0; w < 4; w++) {
        int word = w4 * 4 + w;
        if (word < iw_) continue;
        int j  = word * 32 + lane;
        int jc = (j < TOPN) ? j : (TOPN - 1);
        float4 bj = g_obox[n][jc];
        float aj  = g_area[n][jc];
        float iw = fmaxf(fminf(bi.z, bj.z) - fmaxf(bi.x, bj.x) + 1.0f, 0.0f);
        float ih = fmaxf(fminf(bi.w, bj.w) - fmaxf(bi.y, bj.y) + 1.0f, 0.0f);
        float inter = iw * ih;
        float iou = inter / (ai + aj - inter);
        bool cond = (j < TOPN) && (iou > NMS_T);
        unsigned bal = __ballot_sync(FULLMASK, cond);
        if (lane == 0) g_iou[n][i][word] = bal;
    }
}

// -------- 3: serial NMS scan (warp 0) + final top-100 emit + reset --------
__global__ __launch_bounds__(1024) void nms_emit_kernel(float* __restrict__ out) {
    __shared__ unsigned s_keepw[32];
    __shared__ int s_warpoff[32];
    __shared__ int s_tot;
    const int n = blockIdx.x;
    const int tid = threadIdx.x;
    const int lane = tid & 31, w = tid >> 5;

    if (tid < 32) s_keepw[tid] = 0u;
    __syncthreads();

    // warp 0: sequential greedy scan with prefetch + early exit
    if (tid < 32) {
        unsigned supp = 0u;
        unsigned vmw  = g_validmask[n][lane];
        const unsigned* __restrict__ M = &g_iou[n][0][0];
        int kept = 0;
        bool early = false;

        unsigned mN[32];
#pragma unroll
        for (int j = 0; j < 32; j++) mN[j] = M[j * 32 + lane];

#pragma unroll 1
        for (int c = 0; c < 32; c++) {
            unsigned m[32];
#pragma unroll
            for (int j = 0; j < 32; j++) m[j] = mN[j];
            if (c < 31) {
#pragma unroll
                for (int j = 0; j < 32; j++) mN[j] = M[((c + 1) * 32 + j) * 32 + lane];
            }
            unsigned cur = __shfl_sync(FULLMASK, supp, c);
            unsigned vw  = __shfl_sync(FULLMASK, vmw, c);
            unsigned vals[32];
#pragma unroll
            for (int j = 0; j < 32; j++) vals[j] = __shfl_sync(FULLMASK, m[j], c);

            unsigned keepw = 0u;
#pragma unroll
            for (int j = 0; j < 32; j++) {
                unsigned ki = (vw >> j) & (~(cur >> j)) & 1u;
                keepw |= ki << j;
                unsigned msk = 0u - ki;
                cur  |= vals[j] & msk;
                supp |= m[j]    & msk;
            }
            if (lane == 0) s_keepw[c] = keepw;
            kept += __popc(keepw);
            if (kept >= POSTN) { early = true; break; }
        }
        if (lane == 0) s_tot = early ? TOPN : kept;
    }
    __syncthreads();

    // parallel ranking: kept (in order), then non-kept (in order)
    const bool in = tid < TOPN;
    int k = (in && ((s_keepw[w] >> lane) & 1u)) ? 1 : 0;
    unsigned wb = __ballot_sync(FULLMASK, k);
    int pre = __popc(wb & ((1u << lane) - 1u));
    if (lane == 0) s_warpoff[w] = __popc(wb);
    __syncthreads();
    if (tid == 0) {
        int s = 0;
        for (int x = 0; x < 32; x++) { int t2 = s_warpoff[x]; s_warpoff[x] = s; s += t2; }
    }
    __syncthreads();

    if (in) {
        int kept_before = s_warpoff[w] + pre;
        int r = k ? kept_before : (s_tot + (tid - kept_before));
        if (r < POSTN) {
            int base_b = n * POSTN * 4;
            int base_s = N_IMG * POSTN * 4 + n * POSTN;
            int base_l = N_IMG * POSTN * 5 + n * POSTN;
            out[base_b + r * 4 + 0] = g_boxes[n][tid][0];
            out[base_b + r * 4 + 1] = g_boxes[n][tid][1];
            out[base_b + r * 4 + 2] = g_boxes[n][tid][2];
            out[base_b + r * 4 + 3] = g_boxes[n][tid][3];
            out[base_s + r] = k ? g_scores[n][tid] : -1.0f;
            out[base_l + r] = k ? (float)g_labels[n][tid] : 0.0f;
        }
    }

    // reset per-replay state for the next graph replay
    if (tid < 32) g_validmask[n][tid] = 0u;
    for (int i = tid; i < 4096; i += 1024) g_hist[n][i] = 0u;
    if (tid == 0) {
        g_count[n] = 0;
        if (n == 0) { g_tick1 = 0; g_tick2 = 0; g_flag1 = 0; g_flag2 = 0; }
    }
}

// ---------------- host launch ----------------
extern "C" void kernel_launch(void* const* d_in, const int* in_sizes, int n_in,
                              void* d_out, int out_size) {
    (void)in_sizes; (void)n_in; (void)out_size;
    const float* box_cls = (const float*)d_in[0];
    const float* box_reg = (const float*)d_in[1];
    const float* anchors = (const float*)d_in[2];
    float* out = (float*)d_out;

    front_kernel<<<dim3(FRONT_BX, N_IMG), 256>>>(box_cls, box_reg, anchors);
    iou_kernel<<<dim3(125, 8, N_IMG), dim3(32, 8)>>>();
    nms_emit_kernel<<<N_IMG, 1024>>>(out);
}